// round 13
// baseline (speedup 1.0000x reference)
#include <cuda_runtime.h>
#include <cuda_fp16.h>
#include <cstdint>
#include <math.h>

// ============================================================================
// EdgeModel, persistent unified-warp fp16 mma.sync kernel (baseline PTX):
//   out[e] = softplus( concat(nf[src], nf[dst], ef[e], gf[batch[src]]) @ W.T ) - log2
// R13 = R12's data path (same statics: W/nf/gf fp16 images, ~13MB) with ONE
// structural change: no producer/consumer split — all 8 warps issue MMAs
// (warp tile 32x64, 2 MMA warps per SMSP) and cooperatively run a cp.async
// lookahead-4 pipeline with one __syncthreads per slab (no mbarriers).
// ef slab is register-staged one tile ahead (LDG -> cvt -> STS, empty commit
// group keeps wait_group arithmetic uniform).
// ============================================================================

#define DN 128
#define DE 64
#define DG 64
#define H  128
#define TILE_E 128
#define THREADS 256
#define NSLAB 6
#define LOOKAHEAD 4
#define SLAB 16384                       // 128 rows x 64 f16 (128B rows)
#define OFF_RING (NSLAB * SLAB)          // 98304 (after resident W)
#define OFF_IDX  (OFF_RING + NSLAB * SLAB)   // 196608
#define SMEM_TOTAL (OFF_IDX + 2 * 3 * TILE_E * 4)   // 199680
#define LOG2F_CONST 0.6931471805599453f

#define SWZ128(off) ((off) ^ (((off) >> 3) & 0x70))

#define N_CAP 50000
#define G_CAP 256

// W image: [6 chunks][128 n x 64 k] fp16, SW128-swizzled rows (128B)
// chunk order: 0-1 nf_src, 2-3 nf_dst, 4 gf, 5 ef  (same as R12)
__device__ uint16_t g_Wimg[NSLAB * 128 * 64];
// fp16 row images (plain row-major): nf [N][128], gf [G][64]
__device__ uint16_t g_nfh[N_CAP * DN];
__device__ uint16_t g_gfh[G_CAP * DG];

__global__ void w_convert_kernel(const float* __restrict__ W) {
    int i = blockIdx.x * 256 + threadIdx.x;      // over 128*384
    if (i >= H * 384) return;
    int n = i / 384, k = i - n * 384;
    int c;
    if (k < 256)      c = k >> 6;   // chunks 0-3 (nf)
    else if (k < 320) c = 5;        // ef -> chunk 5
    else              c = 4;        // gf -> chunk 4
    int kk = k & 63;
    __half h = __float2half_rn(W[i]);
    *(uint16_t*)((char*)g_Wimg + (size_t)c * SLAB + SWZ128((uint32_t)(n * 128 + kk * 2)))
        = __half_as_ushort(h);
}

__global__ void nf_convert_kernel(const float* __restrict__ nf, int total4) {
    int i = blockIdx.x * 256 + threadIdx.x;
    if (i >= total4) return;
    float4 v = ((const float4*)nf)[i];
    __half2 a = __floats2half2_rn(v.x, v.y);
    __half2 b = __floats2half2_rn(v.z, v.w);
    uint2 pk; pk.x = *(uint32_t*)&a; pk.y = *(uint32_t*)&b;
    ((uint2*)g_nfh)[i] = pk;
}

__global__ void gf_convert_kernel(const float* __restrict__ gf, int total4) {
    int i = blockIdx.x * 256 + threadIdx.x;
    if (i >= total4) return;
    float4 v = ((const float4*)gf)[i];
    __half2 a = __floats2half2_rn(v.x, v.y);
    __half2 b = __floats2half2_rn(v.z, v.w);
    uint2 pk; pk.x = *(uint32_t*)&a; pk.y = *(uint32_t*)&b;
    ((uint2*)g_gfh)[i] = pk;
}

__device__ __forceinline__ uint32_t smem_u32(const void* p) {
    uint32_t a;
    asm("{ .reg .u64 t; cvta.to.shared.u64 t, %1; cvt.u32.u64 %0, t; }" : "=r"(a) : "l"(p));
    return a;
}
__device__ __forceinline__ void ldsm_x4(uint32_t* r, uint32_t addr) {
    asm volatile("ldmatrix.sync.aligned.m8n8.x4.shared.b16 {%0,%1,%2,%3}, [%4];"
                 : "=r"(r[0]), "=r"(r[1]), "=r"(r[2]), "=r"(r[3]) : "r"(addr));
}
__device__ __forceinline__ void cp_async16(uint32_t dst, const void* src) {
    asm volatile("cp.async.cg.shared.global [%0], [%1], 16;" :: "r"(dst), "l"(src));
}
__device__ __forceinline__ void mma_f16(float* d, const uint32_t* a, uint32_t b0, uint32_t b1) {
    asm volatile(
        "mma.sync.aligned.m16n8k16.row.col.f32.f16.f16.f32 "
        "{%0,%1,%2,%3}, {%4,%5,%6,%7}, {%8,%9}, {%0,%1,%2,%3};"
        : "+f"(d[0]), "+f"(d[1]), "+f"(d[2]), "+f"(d[3])
        : "r"(a[0]), "r"(a[1]), "r"(a[2]), "r"(a[3]), "r"(b0), "r"(b1));
}
__device__ __forceinline__ float softplus_shift(float h) {
    return fmaxf(h, 0.0f) + __logf(1.0f + __expf(-fabsf(h))) - LOG2F_CONST;
}

__global__ __launch_bounds__(THREADS, 1)
void edge_uni_kernel(const float* __restrict__ ef,
                     const int*   __restrict__ ei,
                     const int*   __restrict__ batch,
                     float*       __restrict__ out,
                     int E, int ntiles)
{
    extern __shared__ __align__(1024) char smem[];
    const uint32_t sbase = smem_u32(smem);
    const int tid  = threadIdx.x;
    const int wid  = tid >> 5;
    const int lane = tid & 31;

    // ---- one-time: resident W copy (96KB) ----
    {
        const char* wsrc = (const char*)g_Wimg;
        #pragma unroll
        for (int j = 0; j < 24; ++j)
            cp_async16(sbase + tid * 16 + j * 4096, wsrc + tid * 16 + j * 4096);
        asm volatile("cp.async.commit_group;" ::: "memory");
        asm volatile("cp.async.wait_group 0;" ::: "memory");
    }

    int* s_idx = (int*)(smem + OFF_IDX);          // [2][3][128] ints

    const int nloc = (blockIdx.x < ntiles) ? ((ntiles - 1 - blockIdx.x) / gridDim.x + 1) : 0;
    if (nloc == 0) return;
    const int gtot = nloc * NSLAB;

    // ---- stage indices for tile 0 into buf 0 ----
    if (tid < TILE_E) {
        int e = blockIdx.x * TILE_E + tid; if (e >= E) e = E - 1;
        const int is = ei[e];
        s_idx[tid]       = is;
        s_idx[128 + tid] = ei[E + e];
        s_idx[256 + tid] = batch[is];
    }
    __syncthreads();

    // ---- ef registers for tile 0 (row er, half eq: 8 float4 = 32 floats) ----
    const int er = tid >> 1;
    const int eq = tid & 1;
    float4 ev[8];
    {
        const float4* p = (const float4*)(ef + (size_t)(blockIdx.x * TILE_E + er) * DE);
        #pragma unroll
        for (int j = 0; j < 8; ++j) ev[j] = p[eq * 8 + j];
    }

    const int l8 = tid & 7;        // 16B chunk within a 128B row
    const int rw = tid >> 3;       // base row (0..31): rows rw, rw+32, rw+64, rw+96

    // issue the loads/stores for global-slab g (caller commits)
    auto issue_slab = [&](int g) {
        const int lt  = g / NSLAB;
        const int sl  = g - lt * NSLAB;
        const int buf = (lt & 1) * 384;
        if (sl < 5) {
            const uint32_t dst0 = sbase + OFF_RING + sl * SLAB;
            #pragma unroll
            for (int j = 0; j < 4; ++j) {
                const int r = rw + j * 32;
                const char* src;
                if (sl < 2)      src = (const char*)g_nfh + (size_t)s_idx[buf + r] * 256 + sl * 128;
                else if (sl < 4) src = (const char*)g_nfh + (size_t)s_idx[buf + 128 + r] * 256 + (sl - 2) * 128;
                else             src = (const char*)g_gfh + (size_t)s_idx[buf + 256 + r] * 128;
                cp_async16(dst0 + SWZ128((uint32_t)(r * 128 + l8 * 16)), src + l8 * 16);
            }
        } else {
            // ef: convert staged registers -> STS into slot 5 (slot freed >=2 barriers ago)
            char* d = smem + OFF_RING + 5 * SLAB;
            #pragma unroll
            for (int j = 0; j < 8; ++j) {
                __half2 a = __floats2half2_rn(ev[j].x, ev[j].y);
                __half2 b = __floats2half2_rn(ev[j].z, ev[j].w);
                uint2 pk; pk.x = *(uint32_t*)&a; pk.y = *(uint32_t*)&b;
                *(uint2*)(d + SWZ128((uint32_t)(er * 128 + eq * 64 + j * 8))) = pk;
            }
            // prefetch ef registers for the next tile (~6 slab-steps of cover)
            const int tn = blockIdx.x + (lt + 1) * gridDim.x;
            if (tn < ntiles) {
                int e = tn * TILE_E + er; if (e >= E) e = E - 1;
                const float4* p = (const float4*)(ef + (size_t)e * DE);
                #pragma unroll
                for (int j = 0; j < 8; ++j) ev[j] = p[eq * 8 + j];
            }
        }
    };

    // ---- prologue: slabs 0..3 of tile 0 (all pure cp.async) ----
    #pragma unroll
    for (int g0 = 0; g0 < LOOKAHEAD; ++g0) {
        issue_slab(g0);
        asm volatile("cp.async.commit_group;" ::: "memory");
    }

    const int wm = wid & 3;       // rows wm*32
    const int wn = wid >> 2;      // cols wn*64

    int g = 0;
    int tile = blockIdx.x;
    for (int lt = 0; lt < nloc; ++lt, tile += gridDim.x) {
        // stage indices for tile lt+1 (first consumed >=2 barriers from now)
        if (lt + 1 < nloc && tid < TILE_E) {
            int e = (tile + gridDim.x) * TILE_E + tid; if (e >= E) e = E - 1;
            int* b = s_idx + ((lt + 1) & 1) * 384;
            const int is = ei[e];
            b[tid]       = is;
            b[128 + tid] = ei[E + e];
            b[256 + tid] = batch[is];
        }

        float acc[2][8][4];
        #pragma unroll
        for (int mt = 0; mt < 2; ++mt)
            #pragma unroll
            for (int nt = 0; nt < 8; ++nt)
                #pragma unroll
                for (int z = 0; z < 4; ++z) acc[mt][nt][z] = 0.0f;

        #pragma unroll 1
        for (int sl = 0; sl < NSLAB; ++sl, ++g) {
            // ensure slab g's group has landed (<=3 newer groups pending)
            asm volatile("cp.async.wait_group 3;" ::: "memory");
            __syncthreads();

            if (g + LOOKAHEAD < gtot) issue_slab(g + LOOKAHEAD);
            asm volatile("cp.async.commit_group;" ::: "memory");

            const uint32_t Abase = sbase + OFF_RING + sl * SLAB;
            const uint32_t Bbase = sbase + sl * SLAB;
            #pragma unroll
            for (int ks = 0; ks < 4; ++ks) {
                uint32_t af[2][4], bf[4][4];
                {
                    const int rofs = lane & 15;
                    const int cofs = ks * 32 + ((lane >> 4) & 1) * 16;
                    #pragma unroll
                    for (int mt = 0; mt < 2; ++mt) {
                        const int row = wm * 32 + mt * 16 + rofs;
                        ldsm_x4(af[mt], Abase + SWZ128((uint32_t)(row * 128 + cofs)));
                    }
                }
                {
                    const int rofs = (lane & 7) + ((lane >> 4) & 1) * 8;
                    const int cofs = ks * 32 + ((lane >> 3) & 1) * 16;
                    #pragma unroll
                    for (int nt = 0; nt < 4; ++nt) {
                        const int row = wn * 64 + nt * 16 + rofs;
                        ldsm_x4(bf[nt], Bbase + SWZ128((uint32_t)(row * 128 + cofs)));
                    }
                }
                #pragma unroll
                for (int mt = 0; mt < 2; ++mt)
                    #pragma unroll
                    for (int nt = 0; nt < 4; ++nt) {
                        mma_f16(acc[mt][2 * nt + 0], af[mt], bf[nt][0], bf[nt][1]);
                        mma_f16(acc[mt][2 * nt + 1], af[mt], bf[nt][2], bf[nt][3]);
                    }
            }
        }

        // ---- epilogue: softplus + store ----
        const int e0 = tile * TILE_E;
        #pragma unroll
        for (int mt = 0; mt < 2; ++mt) {
            const int r0 = e0 + wm * 32 + mt * 16 + (lane >> 2);
            const int r1 = r0 + 8;
            #pragma unroll
            for (int nt = 0; nt < 8; ++nt) {
                const int col = wn * 64 + nt * 8 + (lane & 3) * 2;
                if (r0 < E) {
                    float2 o;
                    o.x = softplus_shift(acc[mt][nt][0]);
                    o.y = softplus_shift(acc[mt][nt][1]);
                    *(float2*)(out + (size_t)r0 * H + col) = o;
                }
                if (r1 < E) {
                    float2 o;
                    o.x = softplus_shift(acc[mt][nt][2]);
                    o.y = softplus_shift(acc[mt][nt][3]);
                    *(float2*)(out + (size_t)r1 * H + col) = o;
                }
            }
        }
    }
}

extern "C" void kernel_launch(void* const* d_in, const int* in_sizes, int n_in,
                              void* d_out, int out_size)
{
    const float* nf    = (const float*)d_in[0];
    const float* ef    = (const float*)d_in[1];
    const float* gf    = (const float*)d_in[2];
    const int*   ei    = (const int*)d_in[3];
    const int*   batch = (const int*)d_in[4];
    const float* W     = (const float*)d_in[5];
    float*       out   = (float*)d_out;

    const int E = in_sizes[1] / DE;              // edge_feats is [E, 64]
    const int N = in_sizes[0] / DN;
    const int G = in_sizes[2] / DG;
    const int ntiles = (E + TILE_E - 1) / TILE_E;

    static int sms = 0;
    if (sms == 0) {
        cudaDeviceGetAttribute(&sms, cudaDevAttrMultiProcessorCount, 0);
        if (sms <= 0) sms = 148;
        cudaFuncSetAttribute(edge_uni_kernel,
                             cudaFuncAttributeMaxDynamicSharedMemorySize, SMEM_TOTAL);
    }

    w_convert_kernel<<<(H * 384 + 255) / 256, 256>>>(W);
    const int nf4 = N * DN / 4;
    nf_convert_kernel<<<(nf4 + 255) / 256, 256>>>(nf, nf4);
    const int gf4 = G * DG / 4;
    gf_convert_kernel<<<(gf4 + 255) / 256, 256>>>(gf, gf4);

    const int grid = (sms < ntiles) ? sms : ntiles;
    edge_uni_kernel<<<grid, THREADS, SMEM_TOTAL>>>(ef, ei, batch, out, E, ntiles);
}

// round 14
// speedup vs baseline: 1.5504x; 1.5504x over previous
#include <cuda_runtime.h>
#include <cuda_fp16.h>
#include <cstdint>
#include <math.h>

// ============================================================================
// EdgeModel, persistent warp-specialized fp16 mma.sync kernel (baseline PTX):
//   out[e] = softplus( concat(nf[src], nf[dst], ef[e], gf[batch[src]]) @ W.T ) - log2
// R14 = R12 (passing, 358us) + ONE change: 384 threads — 8 consumer warps
// (warp tile 32x64, 2 MMA warps/SMSP) + 4 producer warps. Same mbarrier slab
// ring, same data path (W/nf/gf fp16 images, ~13MB statics), ef chunk last.
// ============================================================================

#define DN 128
#define DE 64
#define DG 64
#define H  128
#define TILE_E 128
#define THREADS 384
#define NCONS 256                        // consumer threads (warps 0-7)
#define NSLAB 6
#define SLAB 16384                       // 128 rows x 64 f16 (128B rows)
#define OFF_RING (NSLAB * SLAB)          // 98304
#define OFF_IDX  (OFF_RING + NSLAB * SLAB)   // 196608
#define OFF_MBAR (OFF_IDX + 3 * TILE_E * 4)
#define SMEM_TOTAL (OFF_MBAR + 128)
#define LOG2F_CONST 0.6931471805599453f

#define SWZ128(off) ((off) ^ (((off) >> 3) & 0x70))

#define N_CAP 50000
#define G_CAP 256

// W image: [6 chunks][128 n x 64 k] fp16, SW128-swizzled rows (128B)
// chunk order: 0-1 nf_src, 2-3 nf_dst, 4 gf, 5 ef
__device__ uint16_t g_Wimg[NSLAB * 128 * 64];
__device__ uint16_t g_nfh[N_CAP * DN];
__device__ uint16_t g_gfh[G_CAP * DG];

__global__ void w_convert_kernel(const float* __restrict__ W) {
    int i = blockIdx.x * 256 + threadIdx.x;      // over 128*384
    if (i >= H * 384) return;
    int n = i / 384, k = i - n * 384;
    int c;
    if (k < 256)      c = k >> 6;   // chunks 0-3 (nf)
    else if (k < 320) c = 5;        // ef -> chunk 5
    else              c = 4;        // gf -> chunk 4
    int kk = k & 63;
    __half h = __float2half_rn(W[i]);
    *(uint16_t*)((char*)g_Wimg + (size_t)c * SLAB + SWZ128((uint32_t)(n * 128 + kk * 2)))
        = __half_as_ushort(h);
}

__global__ void nf_convert_kernel(const float* __restrict__ nf, int total4) {
    int i = blockIdx.x * 256 + threadIdx.x;
    if (i >= total4) return;
    float4 v = ((const float4*)nf)[i];
    __half2 a = __floats2half2_rn(v.x, v.y);
    __half2 b = __floats2half2_rn(v.z, v.w);
    uint2 pk; pk.x = *(uint32_t*)&a; pk.y = *(uint32_t*)&b;
    ((uint2*)g_nfh)[i] = pk;
}

__global__ void gf_convert_kernel(const float* __restrict__ gf, int total4) {
    int i = blockIdx.x * 256 + threadIdx.x;
    if (i >= total4) return;
    float4 v = ((const float4*)gf)[i];
    __half2 a = __floats2half2_rn(v.x, v.y);
    __half2 b = __floats2half2_rn(v.z, v.w);
    uint2 pk; pk.x = *(uint32_t*)&a; pk.y = *(uint32_t*)&b;
    ((uint2*)g_gfh)[i] = pk;
}

__device__ __forceinline__ uint32_t smem_u32(const void* p) {
    uint32_t a;
    asm("{ .reg .u64 t; cvta.to.shared.u64 t, %1; cvt.u32.u64 %0, t; }" : "=r"(a) : "l"(p));
    return a;
}
__device__ __forceinline__ void ldsm_x4(uint32_t* r, uint32_t addr) {
    asm volatile("ldmatrix.sync.aligned.m8n8.x4.shared.b16 {%0,%1,%2,%3}, [%4];"
                 : "=r"(r[0]), "=r"(r[1]), "=r"(r[2]), "=r"(r[3]) : "r"(addr));
}
__device__ __forceinline__ void cp_async16(uint32_t dst, const void* src) {
    asm volatile("cp.async.cg.shared.global [%0], [%1], 16;" :: "r"(dst), "l"(src));
}
__device__ __forceinline__ void mma_f16(float* d, const uint32_t* a, uint32_t b0, uint32_t b1) {
    asm volatile(
        "mma.sync.aligned.m16n8k16.row.col.f32.f16.f16.f32 "
        "{%0,%1,%2,%3}, {%4,%5,%6,%7}, {%8,%9}, {%0,%1,%2,%3};"
        : "+f"(d[0]), "+f"(d[1]), "+f"(d[2]), "+f"(d[3])
        : "r"(a[0]), "r"(a[1]), "r"(a[2]), "r"(a[3]), "r"(b0), "r"(b1));
}
__device__ __forceinline__ float softplus_shift(float h) {
    return fmaxf(h, 0.0f) + __logf(1.0f + __expf(-fabsf(h))) - LOG2F_CONST;
}

#define MBAR_INIT(mbar, cnt) \
    asm volatile("mbarrier.init.shared.b64 [%0], %1;" \
        :: "r"((uint32_t)(mbar)), "r"((uint32_t)(cnt)) : "memory")
#define MBAR_ARRIVE(mbar) \
    asm volatile("mbarrier.arrive.shared.b64 _, [%0];" :: "r"((uint32_t)(mbar)) : "memory")
#define MBAR_WAIT(mbar, parity) do { \
    uint32_t _m = (uint32_t)(mbar); uint32_t _p = (uint32_t)(parity); uint32_t _d; \
    asm volatile("{\n\t.reg .pred p;\n\t" \
        "mbarrier.try_wait.parity.acquire.cta.shared::cta.b64 p, [%1], %2;\n\t" \
        "selp.b32 %0, 1, 0, p;\n\t}" : "=r"(_d) : "r"(_m), "r"(_p) : "memory"); \
    if (!_d) { \
        asm volatile("{\n\t.reg .pred P1;\n\tWL_%=:\n\t" \
            "mbarrier.try_wait.parity.acquire.cta.shared::cta.b64 P1, [%0], %1, 0x989680;\n\t" \
            "@P1 bra.uni WD_%=;\n\tbra.uni WL_%=;\n\tWD_%=:\n\t}" \
            :: "r"(_m), "r"(_p) : "memory"); \
    } } while (0)

__global__ __launch_bounds__(THREADS, 1)
void edge_ws_kernel(const float* __restrict__ ef,
                    const int*   __restrict__ ei,
                    const int*   __restrict__ batch,
                    float*       __restrict__ out,
                    int E, int ntiles)
{
    extern __shared__ __align__(1024) char smem[];
    const uint32_t sbase = smem_u32(smem);
    const int tid  = threadIdx.x;
    const int wid  = tid >> 5;
    const int lane = tid & 31;

    // ---- one-time: resident W copy (96KB, 384 threads x 16 chunks) ----
    {
        const char* wsrc = (const char*)g_Wimg;
        #pragma unroll
        for (int j = 0; j < 16; ++j)
            cp_async16(sbase + tid * 16 + j * 6144, wsrc + tid * 16 + j * 6144);
        asm volatile("cp.async.commit_group;" ::: "memory");
        asm volatile("cp.async.wait_group 0;" ::: "memory");
    }
    if (tid == 0) {
        #pragma unroll
        for (int s = 0; s < NSLAB; ++s) {
            MBAR_INIT(sbase + OFF_MBAR + s * 8, 128);        // full[s]: producer threads
            MBAR_INIT(sbase + OFF_MBAR + 48 + s * 8, NCONS); // empty[s]: consumer threads
        }
    }
    __syncthreads();   // last block-wide barrier

    if (wid >= 8) {
        // ======================= PRODUCER (warps 8-11) =======================
        const int pw    = wid - 8;
        const int wrow0 = pw * 32;
        int* s_src = (int*)(smem + OFF_IDX);
        int* s_dst = s_src + TILE_E;
        int* s_g   = s_dst + TILE_E;
        const int l8 = lane & 7;       // 16B chunk within row
        const int r4 = lane >> 3;      // row within 4-row group
        int tcnt = 0;
        for (int tile = blockIdx.x; tile < ntiles; tile += gridDim.x, ++tcnt) {
            {
                const int e  = tile * TILE_E + wrow0 + lane;
                const int ee = (e < E) ? e : 0;
                const int is = ei[ee];
                s_src[wrow0 + lane] = is;
                s_dst[wrow0 + lane] = ei[E + ee];
                s_g[wrow0 + lane]   = batch[is];
            }
            __syncwarp();

            const uint32_t ew_par = (tcnt & 1) ^ 1;
            const uint32_t ring   = sbase + OFF_RING;

            // ---- slabs 0-4: pure cp.async ----
            #pragma unroll
            for (int sl = 0; sl < 5; ++sl) {
                if (tcnt > 0) MBAR_WAIT(sbase + OFF_MBAR + 48 + sl * 8, ew_par);
                #pragma unroll
                for (int g = 0; g < 8; ++g) {
                    const int r = wrow0 + g * 4 + r4;
                    const char* src;
                    if (sl < 2)      src = (const char*)g_nfh + (size_t)s_src[r] * 256 + sl * 128;
                    else if (sl < 4) src = (const char*)g_nfh + (size_t)s_dst[r] * 256 + (sl - 2) * 128;
                    else             src = (const char*)g_gfh + (size_t)s_g[r] * 128;
                    cp_async16(ring + sl * SLAB + SWZ128((uint32_t)(r * 128 + l8 * 16)),
                               src + l8 * 16);
                }
                asm volatile("cp.async.commit_group;" ::: "memory");
            }
            asm volatile("cp.async.wait_group 4;" ::: "memory");
            MBAR_ARRIVE(sbase + OFF_MBAR + 0 * 8);
            asm volatile("cp.async.wait_group 3;" ::: "memory");
            MBAR_ARRIVE(sbase + OFF_MBAR + 1 * 8);
            asm volatile("cp.async.wait_group 2;" ::: "memory");
            MBAR_ARRIVE(sbase + OFF_MBAR + 2 * 8);
            asm volatile("cp.async.wait_group 1;" ::: "memory");
            MBAR_ARRIVE(sbase + OFF_MBAR + 3 * 8);
            asm volatile("cp.async.wait_group 0;" ::: "memory");
            MBAR_ARRIVE(sbase + OFF_MBAR + 4 * 8);

            // ---- slab 5: ef fp32 LDG+cvt+STS, overlapped with consumer ----
            if (tcnt > 0) MBAR_WAIT(sbase + OFF_MBAR + 48 + 5 * 8, ew_par);
            {
                char* dst = smem + OFF_RING + 5 * SLAB;
                #pragma unroll
                for (int g = 0; g < 8; ++g) {
                    const int r  = wrow0 + g * 4 + r4;
                    const int e  = tile * TILE_E + r;
                    const int ee = (e < E) ? e : 0;
                    const float* rp = ef + (size_t)ee * DE;
                    float4 v0 = *(const float4*)(rp + l8 * 4);
                    float4 v1 = *(const float4*)(rp + 32 + l8 * 4);
                    __half2 a0 = __floats2half2_rn(v0.x, v0.y);
                    __half2 b0 = __floats2half2_rn(v0.z, v0.w);
                    __half2 a1 = __floats2half2_rn(v1.x, v1.y);
                    __half2 b1 = __floats2half2_rn(v1.z, v1.w);
                    uint2 p0; p0.x = *(uint32_t*)&a0; p0.y = *(uint32_t*)&b0;
                    uint2 p1; p1.x = *(uint32_t*)&a1; p1.y = *(uint32_t*)&b1;
                    *(uint2*)(dst + SWZ128((uint32_t)(r * 128 + l8 * 8)))      = p0;
                    *(uint2*)(dst + SWZ128((uint32_t)(r * 128 + 64 + l8 * 8))) = p1;
                }
            }
            MBAR_ARRIVE(sbase + OFF_MBAR + 5 * 8);
        }
    } else {
        // ======================= CONSUMER (warps 0-7) =======================
        const int wm = wid & 3;       // rows wm*32
        const int wn = wid >> 2;      // cols wn*64
        int tcnt = 0;
        for (int tile = blockIdx.x; tile < ntiles; tile += gridDim.x, ++tcnt) {
            const int e0 = tile * TILE_E;
            float acc[2][8][4];
            #pragma unroll
            for (int mt = 0; mt < 2; ++mt)
                #pragma unroll
                for (int nt = 0; nt < 8; ++nt)
                    #pragma unroll
                    for (int z = 0; z < 4; ++z) acc[mt][nt][z] = 0.0f;

            const uint32_t fw_par = tcnt & 1;
            #pragma unroll 1
            for (int sl = 0; sl < NSLAB; ++sl) {
                MBAR_WAIT(sbase + OFF_MBAR + sl * 8, fw_par);
                const uint32_t Abase = sbase + OFF_RING + sl * SLAB;
                const uint32_t Bbase = sbase + sl * SLAB;
                #pragma unroll
                for (int ks = 0; ks < 4; ++ks) {
                    uint32_t af[2][4], bf[4][4];
                    {
                        const int rofs = lane & 15;
                        const int cofs = ks * 32 + ((lane >> 4) & 1) * 16;
                        #pragma unroll
                        for (int mt = 0; mt < 2; ++mt) {
                            const int row = wm * 32 + mt * 16 + rofs;
                            ldsm_x4(af[mt], Abase + SWZ128((uint32_t)(row * 128 + cofs)));
                        }
                    }
                    {
                        const int rofs = (lane & 7) + ((lane >> 4) & 1) * 8;
                        const int cofs = ks * 32 + ((lane >> 3) & 1) * 16;
                        #pragma unroll
                        for (int nt = 0; nt < 4; ++nt) {
                            const int row = wn * 64 + nt * 16 + rofs;
                            ldsm_x4(bf[nt], Bbase + SWZ128((uint32_t)(row * 128 + cofs)));
                        }
                    }
                    #pragma unroll
                    for (int mt = 0; mt < 2; ++mt)
                        #pragma unroll
                        for (int nt = 0; nt < 4; ++nt) {
                            mma_f16(acc[mt][2 * nt + 0], af[mt], bf[nt][0], bf[nt][1]);
                            mma_f16(acc[mt][2 * nt + 1], af[mt], bf[nt][2], bf[nt][3]);
                        }
                }
                MBAR_ARRIVE(sbase + OFF_MBAR + 48 + sl * 8);
            }

            // ---- epilogue: softplus + store ----
            #pragma unroll
            for (int mt = 0; mt < 2; ++mt) {
                const int r0 = e0 + wm * 32 + mt * 16 + (lane >> 2);
                const int r1 = r0 + 8;
                #pragma unroll
                for (int nt = 0; nt < 8; ++nt) {
                    const int col = wn * 64 + nt * 8 + (lane & 3) * 2;
                    if (r0 < E) {
                        float2 o;
                        o.x = softplus_shift(acc[mt][nt][0]);
                        o.y = softplus_shift(acc[mt][nt][1]);
                        *(float2*)(out + (size_t)r0 * H + col) = o;
                    }
                    if (r1 < E) {
                        float2 o;
                        o.x = softplus_shift(acc[mt][nt][2]);
                        o.y = softplus_shift(acc[mt][nt][3]);
                        *(float2*)(out + (size_t)r1 * H + col) = o;
                    }
                }
            }
        }
    }
}

extern "C" void kernel_launch(void* const* d_in, const int* in_sizes, int n_in,
                              void* d_out, int out_size)
{
    const float* nf    = (const float*)d_in[0];
    const float* ef    = (const float*)d_in[1];
    const float* gf    = (const float*)d_in[2];
    const int*   ei    = (const int*)d_in[3];
    const int*   batch = (const int*)d_in[4];
    const float* W     = (const float*)d_in[5];
    float*       out   = (float*)d_out;

    const int E = in_sizes[1] / DE;              // edge_feats is [E, 64]
    const int N = in_sizes[0] / DN;
    const int G = in_sizes[2] / DG;
    const int ntiles = (E + TILE_E - 1) / TILE_E;

    static int sms = 0;
    if (sms == 0) {
        cudaDeviceGetAttribute(&sms, cudaDevAttrMultiProcessorCount, 0);
        if (sms <= 0) sms = 148;
        cudaFuncSetAttribute(edge_ws_kernel,
                             cudaFuncAttributeMaxDynamicSharedMemorySize, SMEM_TOTAL);
    }

    w_convert_kernel<<<(H * 384 + 255) / 256, 256>>>(W);
    const int nf4 = N * DN / 4;
    nf_convert_kernel<<<(nf4 + 255) / 256, 256>>>(nf, nf4);
    const int gf4 = G * DG / 4;
    gf_convert_kernel<<<(gf4 + 255) / 256, 256>>>(gf, gf4);

    const int grid = (sms < ntiles) ? sms : ntiles;
    edge_ws_kernel<<<grid, THREADS, SMEM_TOTAL>>>(ef, ei, batch, out, E, ntiles);
}

// round 15
// speedup vs baseline: 1.8052x; 1.1644x over previous
#include <cuda_runtime.h>
#include <cuda_fp16.h>
#include <cstdint>
#include <math.h>

// ============================================================================
// EdgeModel factorized (R15):
//   h[e] = nf[src]@W1.T + nf[dst]@W2.T + ef[e]@W3.T + gf[batch[src]]@W4.T
// Precompute (per launch):
//   Pg = gf@W4.T               [256,128] fp32
//   P[n] = concat( nf[n]@W1.T + Pg[batch[n]] , nf[n]@W2.T )  [50K,256] fp16
// Main (persistent, R14 producer/consumer skeleton):
//   out[e] = softplus( ef[e]@W3.T + P[src][0:128] + P[dst][128:256] ) - log2
// Per-tile: ONE K=64 HMMA slab + gathered P-row adds in the epilogue.
// ============================================================================

#define DN 128
#define DE 64
#define DG 64
#define H  128
#define TILE_E 128
#define THREADS 384
#define NCONS 256
#define SLAB 16384
#define LOG2F_CONST 0.6931471805599453f

#define SWZ128(off) ((off) ^ (((off) >> 3) & 0x70))

#define N_CAP 50000
#define G_CAP 256

// ---- smem layout (main kernel) ----
#define OFF_W3   0                         // 16KB resident W3 (ef chunk)
#define OFF_EF   16384                     // 2 x 16KB ef slabs
#define PSTRIDE  528                       // 512B row (P1'|P2) + 16B pad
#define PSTAGE   (128 * PSTRIDE)           // 67584
#define OFF_P    (16384 + 2 * 16384)       // 49152, 2 x PSTAGE
#define OFF_IDX  (OFF_P + 2 * PSTAGE)      // 184320, 256 ints
#define OFF_MBAR (OFF_IDX + 1024)          // 185344
#define SMEM_TOTAL (OFF_MBAR + 64)

// ---- statics ----
// W image: [6 chunks][128 n x 64 k] fp16 SW128; chunks 0-1=W1, 2-3=W2, 4=W4(gf), 5=W3(ef)
__device__ uint16_t g_Wimg[6 * 128 * 64];
__device__ __half   g_P[N_CAP * 256];      // 25.6MB
__device__ float    g_Pg[G_CAP * H];       // 128KB

// ---------------- pre-kernels ----------------
__global__ void w_convert_kernel(const float* __restrict__ W) {
    int i = blockIdx.x * 256 + threadIdx.x;      // over 128*384
    if (i >= H * 384) return;
    int n = i / 384, k = i - n * 384;
    int c;
    if (k < 256)      c = k >> 6;   // W1,W2 -> chunks 0-3
    else if (k < 320) c = 5;        // ef -> chunk 5
    else              c = 4;        // gf -> chunk 4
    int kk = k & 63;
    __half h = __float2half_rn(W[i]);
    *(uint16_t*)((char*)g_Wimg + (size_t)c * SLAB + SWZ128((uint32_t)(n * 128 + kk * 2)))
        = __half_as_ushort(h);
}

__global__ void pg_kernel(const float* __restrict__ gf, const float* __restrict__ W, int G) {
    int i = blockIdx.x * 256 + threadIdx.x;
    if (i >= G * H) return;
    int g = i >> 7, o = i & 127;
    float s = 0.0f;
    #pragma unroll 8
    for (int k = 0; k < DG; ++k)
        s += gf[g * DG + k] * W[o * 384 + 320 + k];
    g_Pg[i] = s;
}

__device__ __forceinline__ uint32_t smem_u32(const void* p) {
    uint32_t a;
    asm("{ .reg .u64 t; cvta.to.shared.u64 t, %1; cvt.u32.u64 %0, t; }" : "=r"(a) : "l"(p));
    return a;
}
__device__ __forceinline__ void ldsm_x4(uint32_t* r, uint32_t addr) {
    asm volatile("ldmatrix.sync.aligned.m8n8.x4.shared.b16 {%0,%1,%2,%3}, [%4];"
                 : "=r"(r[0]), "=r"(r[1]), "=r"(r[2]), "=r"(r[3]) : "r"(addr));
}
__device__ __forceinline__ void cp_async16(uint32_t dst, const void* src) {
    asm volatile("cp.async.cg.shared.global [%0], [%1], 16;" :: "r"(dst), "l"(src));
}
__device__ __forceinline__ void mma_f16(float* d, const uint32_t* a, uint32_t b0, uint32_t b1) {
    asm volatile(
        "mma.sync.aligned.m16n8k16.row.col.f32.f16.f16.f32 "
        "{%0,%1,%2,%3}, {%4,%5,%6,%7}, {%8,%9}, {%0,%1,%2,%3};"
        : "+f"(d[0]), "+f"(d[1]), "+f"(d[2]), "+f"(d[3])
        : "r"(a[0]), "r"(a[1]), "r"(a[2]), "r"(a[3]), "r"(b0), "r"(b1));
}
__device__ __forceinline__ float softplus_shift(float h) {
    return fmaxf(h, 0.0f) + __logf(1.0f + __expf(-fabsf(h))) - LOG2F_CONST;
}

#define MBAR_INIT(mbar, cnt) \
    asm volatile("mbarrier.init.shared.b64 [%0], %1;" \
        :: "r"((uint32_t)(mbar)), "r"((uint32_t)(cnt)) : "memory")
#define MBAR_ARRIVE(mbar) \
    asm volatile("mbarrier.arrive.shared.b64 _, [%0];" :: "r"((uint32_t)(mbar)) : "memory")
#define MBAR_WAIT(mbar, parity) do { \
    uint32_t _m = (uint32_t)(mbar); uint32_t _p = (uint32_t)(parity); uint32_t _d; \
    asm volatile("{\n\t.reg .pred p;\n\t" \
        "mbarrier.try_wait.parity.acquire.cta.shared::cta.b64 p, [%1], %2;\n\t" \
        "selp.b32 %0, 1, 0, p;\n\t}" : "=r"(_d) : "r"(_m), "r"(_p) : "memory"); \
    if (!_d) { \
        asm volatile("{\n\t.reg .pred P1;\n\tWL_%=:\n\t" \
            "mbarrier.try_wait.parity.acquire.cta.shared::cta.b64 P1, [%0], %1, 0x989680;\n\t" \
            "@P1 bra.uni WD_%=;\n\tbra.uni WL_%=;\n\tWD_%=:\n\t}" \
            :: "r"(_m), "r"(_p) : "memory"); \
    } } while (0)

// ---------------- prep GEMM: P[node][colbase:colbase+128] = nf@Wc0.T (+Pg) ----------------
__global__ __launch_bounds__(256, 1)
void prep_kernel(const float* __restrict__ nf, const int* __restrict__ batch,
                 int Nn, int c0, int colbase, int addpg)
{
    extern __shared__ __align__(1024) char smem[];
    const uint32_t sbase = smem_u32(smem);
    const int tid  = threadIdx.x;
    const int wid  = tid >> 5;
    const int lane = tid & 31;
    const int blk  = blockIdx.x;

    // copy W chunks c0, c0+1 (32KB) to smem[32768..65536)
    {
        const uint4* wsrc = (const uint4*)((const char*)g_Wimg + (size_t)c0 * SLAB);
        uint4* wdst = (uint4*)(smem + 32768);
        #pragma unroll
        for (int j = 0; j < 8; ++j)
            wdst[tid + j * 256] = wsrc[tid + j * 256];
    }
    // stage A: nf rows (2 slabs of 64 cols) fp32->fp16 swizzled
    {
        const int r = tid >> 1, q = tid & 1;
        int node = blk * TILE_E + r; if (node >= Nn) node = Nn - 1;
        const float* rp = nf + (size_t)node * DN;
        #pragma unroll
        for (int sl = 0; sl < 2; ++sl) {
            char* ab = smem + sl * SLAB;
            #pragma unroll
            for (int j = 0; j < 8; ++j) {
                const int col = q * 32 + j * 4;
                float4 v = *(const float4*)(rp + sl * 64 + col);
                __half2 a = __floats2half2_rn(v.x, v.y);
                __half2 b = __floats2half2_rn(v.z, v.w);
                uint2 pk; pk.x = *(uint32_t*)&a; pk.y = *(uint32_t*)&b;
                *(uint2*)(ab + SWZ128((uint32_t)(r * 128 + col * 2))) = pk;
            }
        }
    }
    __syncthreads();

    const int wm = wid & 3, wn = wid >> 2;
    float acc[2][8][4];
    #pragma unroll
    for (int mt = 0; mt < 2; ++mt)
        #pragma unroll
        for (int nt = 0; nt < 8; ++nt)
            #pragma unroll
            for (int z = 0; z < 4; ++z) acc[mt][nt][z] = 0.0f;

    #pragma unroll
    for (int sl = 0; sl < 2; ++sl) {
        const uint32_t Abase = sbase + sl * SLAB;
        const uint32_t Bbase = sbase + 32768 + sl * SLAB;
        #pragma unroll
        for (int ks = 0; ks < 4; ++ks) {
            uint32_t af[2][4], bf[4][4];
            {
                const int rofs = lane & 15;
                const int cofs = ks * 32 + ((lane >> 4) & 1) * 16;
                #pragma unroll
                for (int mt = 0; mt < 2; ++mt) {
                    const int row = wm * 32 + mt * 16 + rofs;
                    ldsm_x4(af[mt], Abase + SWZ128((uint32_t)(row * 128 + cofs)));
                }
            }
            {
                const int rofs = (lane & 7) + ((lane >> 4) & 1) * 8;
                const int cofs = ks * 32 + ((lane >> 3) & 1) * 16;
                #pragma unroll
                for (int nt = 0; nt < 4; ++nt) {
                    const int row = wn * 64 + nt * 16 + rofs;
                    ldsm_x4(bf[nt], Bbase + SWZ128((uint32_t)(row * 128 + cofs)));
                }
            }
            #pragma unroll
            for (int mt = 0; mt < 2; ++mt)
                #pragma unroll
                for (int nt = 0; nt < 4; ++nt) {
                    mma_f16(acc[mt][2 * nt + 0], af[mt], bf[nt][0], bf[nt][1]);
                    mma_f16(acc[mt][2 * nt + 1], af[mt], bf[nt][2], bf[nt][3]);
                }
        }
    }

    // epilogue: (+Pg[batch[n]]) -> fp16 store into g_P[n][colbase + col]
    #pragma unroll
    for (int mt = 0; mt < 2; ++mt) {
        const int n0 = blk * TILE_E + wm * 32 + mt * 16 + (lane >> 2);
        const int n1 = n0 + 8;
        #pragma unroll
        for (int nt = 0; nt < 8; ++nt) {
            const int col = wn * 64 + nt * 8 + (lane & 3) * 2;
            if (n0 < Nn) {
                float f0 = acc[mt][nt][0], f1 = acc[mt][nt][1];
                if (addpg) {
                    const float* pg = g_Pg + (size_t)batch[n0] * H + col;
                    f0 += pg[0]; f1 += pg[1];
                }
                __half2 hv = __floats2half2_rn(f0, f1);
                *(__half2*)(g_P + (size_t)n0 * 256 + colbase + col) = hv;
            }
            if (n1 < Nn) {
                float f0 = acc[mt][nt][2], f1 = acc[mt][nt][3];
                if (addpg) {
                    const float* pg = g_Pg + (size_t)batch[n1] * H + col;
                    f0 += pg[0]; f1 += pg[1];
                }
                __half2 hv = __floats2half2_rn(f0, f1);
                *(__half2*)(g_P + (size_t)n1 * 256 + colbase + col) = hv;
            }
        }
    }
}

// ---------------- main kernel ----------------
__global__ __launch_bounds__(THREADS, 1)
void edge_fact_kernel(const float* __restrict__ ef,
                      const int*   __restrict__ ei,
                      float*       __restrict__ out,
                      int E, int ntiles)
{
    extern __shared__ __align__(1024) char smem[];
    const uint32_t sbase = smem_u32(smem);
    const int tid  = threadIdx.x;
    const int wid  = tid >> 5;
    const int lane = tid & 31;

    // one-time: resident W3 (16KB = chunk 5) + mbarrier init
    {
        const uint4* wsrc = (const uint4*)((const char*)g_Wimg + 5 * SLAB);
        uint4* wdst = (uint4*)(smem + OFF_W3);
        #pragma unroll
        for (int j = 0; j < 3; ++j) {
            int i = tid + j * THREADS;
            if (i < 1024) wdst[i] = wsrc[i];
        }
    }
    if (tid == 0) {
        #pragma unroll
        for (int p = 0; p < 2; ++p) {
            MBAR_INIT(sbase + OFF_MBAR + p * 8, 128);        // full_ef[p]
            MBAR_INIT(sbase + OFF_MBAR + 16 + p * 8, 128);   // full_P[p]
            MBAR_INIT(sbase + OFF_MBAR + 32 + p * 8, NCONS); // empty[p]
        }
    }
    __syncthreads();

    if (wid >= 8) {
        // =================== PRODUCER (warps 8-11) ===================
        const int pw    = wid - 8;
        const int wrow0 = pw * 32;
        int* s_src = (int*)(smem + OFF_IDX);
        int* s_dst = s_src + TILE_E;
        const int l8 = lane & 7;
        const int r4 = lane >> 3;
        const int half = lane >> 4;        // 0: src-half, 1: dst-half
        const int li   = lane & 15;
        int tcnt = 0;
        for (int tile = blockIdx.x; tile < ntiles; tile += gridDim.x, ++tcnt) {
            const int p = tcnt & 1;
            {
                int e = tile * TILE_E + wrow0 + lane; if (e >= E) e = E - 1;
                s_src[wrow0 + lane] = ei[e];
                s_dst[wrow0 + lane] = ei[E + e];
            }
            __syncwarp();

            if (tcnt >= 2) MBAR_WAIT(sbase + OFF_MBAR + 32 + p * 8, (((tcnt >> 1) & 1) ^ 1));

            // ---- P rows via cp.async: lanes 0-15 = P1'(src), 16-31 = P2(dst) ----
            {
                const uint32_t pb = sbase + OFF_P + p * PSTAGE;
                #pragma unroll
                for (int rp = 0; rp < 32; ++rp) {
                    const int r = wrow0 + rp;
                    const int idx = half ? s_dst[r] : s_src[r];
                    const char* src = (const char*)g_P + (size_t)idx * 512 + half * 256 + li * 16;
                    cp_async16(pb + r * PSTRIDE + lane * 16, src);
                }
                asm volatile("cp.async.commit_group;" ::: "memory");
            }

            // ---- ef slab: LDG fp32 + cvt + STS swizzled ----
            {
                char* dst = smem + OFF_EF + p * SLAB;
                #pragma unroll
                for (int g = 0; g < 8; ++g) {
                    const int r  = wrow0 + g * 4 + r4;
                    int e = tile * TILE_E + r; if (e >= E) e = E - 1;
                    const float* rp = ef + (size_t)e * DE;
                    float4 v0 = *(const float4*)(rp + l8 * 4);
                    float4 v1 = *(const float4*)(rp + 32 + l8 * 4);
                    __half2 a0 = __floats2half2_rn(v0.x, v0.y);
                    __half2 b0 = __floats2half2_rn(v0.z, v0.w);
                    __half2 a1 = __floats2half2_rn(v1.x, v1.y);
                    __half2 b1 = __floats2half2_rn(v1.z, v1.w);
                    uint2 p0; p0.x = *(uint32_t*)&a0; p0.y = *(uint32_t*)&b0;
                    uint2 p1; p1.x = *(uint32_t*)&a1; p1.y = *(uint32_t*)&b1;
                    *(uint2*)(dst + SWZ128((uint32_t)(r * 128 + l8 * 8)))      = p0;
                    *(uint2*)(dst + SWZ128((uint32_t)(r * 128 + 64 + l8 * 8))) = p1;
                }
            }
            MBAR_ARRIVE(sbase + OFF_MBAR + p * 8);          // full_ef

            asm volatile("cp.async.wait_group 0;" ::: "memory");
            MBAR_ARRIVE(sbase + OFF_MBAR + 16 + p * 8);     // full_P
        }
    } else {
        // =================== CONSUMER (warps 0-7) ===================
        const int wm = wid & 3;
        const int wn = wid >> 2;
        int tcnt = 0;
        for (int tile = blockIdx.x; tile < ntiles; tile += gridDim.x, ++tcnt) {
            const int p  = tcnt & 1;
            const uint32_t fw = (tcnt >> 1) & 1;
            const int e0 = tile * TILE_E;

            float acc[2][8][4];
            #pragma unroll
            for (int mt = 0; mt < 2; ++mt)
                #pragma unroll
                for (int nt = 0; nt < 8; ++nt)
                    #pragma unroll
                    for (int z = 0; z < 4; ++z) acc[mt][nt][z] = 0.0f;

            MBAR_WAIT(sbase + OFF_MBAR + p * 8, fw);        // full_ef

            // ---- single K=64 slab: A=ef, B=W3 resident ----
            {
                const uint32_t Abase = sbase + OFF_EF + p * SLAB;
                const uint32_t Bbase = sbase + OFF_W3;
                #pragma unroll
                for (int ks = 0; ks < 4; ++ks) {
                    uint32_t af[2][4], bf[4][4];
                    {
                        const int rofs = lane & 15;
                        const int cofs = ks * 32 + ((lane >> 4) & 1) * 16;
                        #pragma unroll
                        for (int mt = 0; mt < 2; ++mt) {
                            const int row = wm * 32 + mt * 16 + rofs;
                            ldsm_x4(af[mt], Abase + SWZ128((uint32_t)(row * 128 + cofs)));
                        }
                    }
                    {
                        const int rofs = (lane & 7) + ((lane >> 4) & 1) * 8;
                        const int cofs = ks * 32 + ((lane >> 3) & 1) * 16;
                        #pragma unroll
                        for (int nt = 0; nt < 4; ++nt) {
                            const int row = wn * 64 + nt * 16 + rofs;
                            ldsm_x4(bf[nt], Bbase + SWZ128((uint32_t)(row * 128 + cofs)));
                        }
                    }
                    #pragma unroll
                    for (int mt = 0; mt < 2; ++mt)
                        #pragma unroll
                        for (int nt = 0; nt < 4; ++nt) {
                            mma_f16(acc[mt][2 * nt + 0], af[mt], bf[nt][0], bf[nt][1]);
                            mma_f16(acc[mt][2 * nt + 1], af[mt], bf[nt][2], bf[nt][3]);
                        }
                }
            }

            MBAR_WAIT(sbase + OFF_MBAR + 16 + p * 8, fw);   // full_P

            // ---- epilogue: + P1'[src] + P2[dst], softplus, store ----
            const char* pb = smem + OFF_P + p * PSTAGE;
            #pragma unroll
            for (int mt = 0; mt < 2; ++mt) {
                const int lr0 = wm * 32 + mt * 16 + (lane >> 2);
                const int lr1 = lr0 + 8;
                const int r0 = e0 + lr0, r1 = e0 + lr1;
                #pragma unroll
                for (int nt = 0; nt < 8; ++nt) {
                    const int col  = wn * 64 + nt * 8 + (lane & 3) * 2;
                    const int colb = col * 2;
                    if (r0 < E) {
                        uint32_t u1 = *(const uint32_t*)(pb + lr0 * PSTRIDE + colb);
                        uint32_t u2 = *(const uint32_t*)(pb + lr0 * PSTRIDE + 256 + colb);
                        float2 f1 = __half22float2(*(__half2*)&u1);
                        float2 f2 = __half22float2(*(__half2*)&u2);
                        float2 o;
                        o.x = softplus_shift(acc[mt][nt][0] + f1.x + f2.x);
                        o.y = softplus_shift(acc[mt][nt][1] + f1.y + f2.y);
                        *(float2*)(out + (size_t)r0 * H + col) = o;
                    }
                    if (r1 < E) {
                        uint32_t u1 = *(const uint32_t*)(pb + lr1 * PSTRIDE + colb);
                        uint32_t u2 = *(const uint32_t*)(pb + lr1 * PSTRIDE + 256 + colb);
                        float2 f1 = __half22float2(*(__half2*)&u1);
                        float2 f2 = __half22float2(*(__half2*)&u2);
                        float2 o;
                        o.x = softplus_shift(acc[mt][nt][2] + f1.x + f2.x);
                        o.y = softplus_shift(acc[mt][nt][3] + f1.y + f2.y);
                        *(float2*)(out + (size_t)r1 * H + col) = o;
                    }
                }
            }
            MBAR_ARRIVE(sbase + OFF_MBAR + 32 + p * 8);     // empty
        }
    }
}

extern "C" void kernel_launch(void* const* d_in, const int* in_sizes, int n_in,
                              void* d_out, int out_size)
{
    const float* nf    = (const float*)d_in[0];
    const float* ef    = (const float*)d_in[1];
    const float* gf    = (const float*)d_in[2];
    const int*   ei    = (const int*)d_in[3];
    const int*   batch = (const int*)d_in[4];
    const float* W     = (const float*)d_in[5];
    float*       out   = (float*)d_out;

    const int E  = in_sizes[1] / DE;             // edge_feats is [E, 64]
    const int Nn = in_sizes[0] / DN;
    const int G  = in_sizes[2] / DG;
    const int ntiles = (E + TILE_E - 1) / TILE_E;

    static int sms = 0;
    if (sms == 0) {
        cudaDeviceGetAttribute(&sms, cudaDevAttrMultiProcessorCount, 0);
        if (sms <= 0) sms = 148;
        cudaFuncSetAttribute(edge_fact_kernel,
                             cudaFuncAttributeMaxDynamicSharedMemorySize, SMEM_TOTAL);
        cudaFuncSetAttribute(prep_kernel,
                             cudaFuncAttributeMaxDynamicSharedMemorySize, 65536);
    }

    w_convert_kernel<<<(H * 384 + 255) / 256, 256>>>(W);
    pg_kernel<<<(G * H + 255) / 256, 256>>>(gf, W, G);
    const int nblk = (Nn + TILE_E - 1) / TILE_E;
    prep_kernel<<<nblk, 256, 65536>>>(nf, batch, Nn, 0, 0, 1);     // W1 half + Pg
    prep_kernel<<<nblk, 256, 65536>>>(nf, batch, Nn, 2, 128, 0);   // W2 half

    const int grid = (sms < ntiles) ? sms : ntiles;
    edge_fact_kernel<<<grid, THREADS, SMEM_TOTAL>>>(ef, ei, out, E, ntiles);
}

// round 16
// speedup vs baseline: 1.8468x; 1.0230x over previous
#include <cuda_runtime.h>
#include <cuda_fp16.h>
#include <cstdint>
#include <math.h>

// ============================================================================
// EdgeModel factorized (R16 = R15 + two latency fixes):
//   h[e] = nf[src]@W1.T + nf[dst]@W2.T + ef[e]@W3.T + gf[batch[src]]@W4.T
// Precompute: Pg = gf@W4.T ; P[n] = ( nf@W1.T + Pg[batch[n]] | nf@W2.T ) fp16
//   -> prep parallelized over halves via gridDim.y=2 (one launch, ~21us)
// Main: out[e] = softplus( ef@W3.T + P[src][:128] + P[dst][128:] ) - log2
//   -> producer ef LDG register-prefetched one tile ahead (latency hidden)
// ============================================================================

#define DN 128
#define DE 64
#define DG 64
#define H  128
#define TILE_E 128
#define THREADS 384
#define NCONS 256
#define SLAB 16384
#define LOG2F_CONST 0.6931471805599453f

#define SWZ128(off) ((off) ^ (((off) >> 3) & 0x70))

#define N_CAP 50000
#define G_CAP 256

// ---- smem layout (main kernel) ----
#define OFF_W3   0                         // 16KB resident W3 (ef chunk)
#define OFF_EF   16384                     // 2 x 16KB ef slabs
#define PSTRIDE  528                       // 512B row (P1'|P2) + 16B pad
#define PSTAGE   (128 * PSTRIDE)           // 67584
#define OFF_P    (16384 + 2 * 16384)       // 49152, 2 x PSTAGE
#define OFF_IDX  (OFF_P + 2 * PSTAGE)      // 184320, 256 ints
#define OFF_MBAR (OFF_IDX + 1024)          // 185344
#define SMEM_TOTAL (OFF_MBAR + 64)

// ---- statics ----
__device__ uint16_t g_Wimg[6 * 128 * 64];  // chunks 0-1=W1, 2-3=W2, 4=W4(gf), 5=W3(ef)
__device__ __half   g_P[N_CAP * 256];      // 25.6MB
__device__ float    g_Pg[G_CAP * H];       // 128KB

// ---------------- pre-kernels ----------------
__global__ void w_convert_kernel(const float* __restrict__ W) {
    int i = blockIdx.x * 256 + threadIdx.x;      // over 128*384
    if (i >= H * 384) return;
    int n = i / 384, k = i - n * 384;
    int c;
    if (k < 256)      c = k >> 6;   // W1,W2 -> chunks 0-3
    else if (k < 320) c = 5;        // ef -> chunk 5
    else              c = 4;        // gf -> chunk 4
    int kk = k & 63;
    __half h = __float2half_rn(W[i]);
    *(uint16_t*)((char*)g_Wimg + (size_t)c * SLAB + SWZ128((uint32_t)(n * 128 + kk * 2)))
        = __half_as_ushort(h);
}

__global__ void pg_kernel(const float* __restrict__ gf, const float* __restrict__ W, int G) {
    int i = blockIdx.x * 256 + threadIdx.x;
    if (i >= G * H) return;
    int g = i >> 7, o = i & 127;
    float s = 0.0f;
    #pragma unroll 8
    for (int k = 0; k < DG; ++k)
        s += gf[g * DG + k] * W[o * 384 + 320 + k];
    g_Pg[i] = s;
}

__device__ __forceinline__ uint32_t smem_u32(const void* p) {
    uint32_t a;
    asm("{ .reg .u64 t; cvta.to.shared.u64 t, %1; cvt.u32.u64 %0, t; }" : "=r"(a) : "l"(p));
    return a;
}
__device__ __forceinline__ void ldsm_x4(uint32_t* r, uint32_t addr) {
    asm volatile("ldmatrix.sync.aligned.m8n8.x4.shared.b16 {%0,%1,%2,%3}, [%4];"
                 : "=r"(r[0]), "=r"(r[1]), "=r"(r[2]), "=r"(r[3]) : "r"(addr));
}
__device__ __forceinline__ void cp_async16(uint32_t dst, const void* src) {
    asm volatile("cp.async.cg.shared.global [%0], [%1], 16;" :: "r"(dst), "l"(src));
}
__device__ __forceinline__ void mma_f16(float* d, const uint32_t* a, uint32_t b0, uint32_t b1) {
    asm volatile(
        "mma.sync.aligned.m16n8k16.row.col.f32.f16.f16.f32 "
        "{%0,%1,%2,%3}, {%4,%5,%6,%7}, {%8,%9}, {%0,%1,%2,%3};"
        : "+f"(d[0]), "+f"(d[1]), "+f"(d[2]), "+f"(d[3])
        : "r"(a[0]), "r"(a[1]), "r"(a[2]), "r"(a[3]), "r"(b0), "r"(b1));
}
__device__ __forceinline__ float softplus_shift(float h) {
    return fmaxf(h, 0.0f) + __logf(1.0f + __expf(-fabsf(h))) - LOG2F_CONST;
}

#define MBAR_INIT(mbar, cnt) \
    asm volatile("mbarrier.init.shared.b64 [%0], %1;" \
        :: "r"((uint32_t)(mbar)), "r"((uint32_t)(cnt)) : "memory")
#define MBAR_ARRIVE(mbar) \
    asm volatile("mbarrier.arrive.shared.b64 _, [%0];" :: "r"((uint32_t)(mbar)) : "memory")
#define MBAR_WAIT(mbar, parity) do { \
    uint32_t _m = (uint32_t)(mbar); uint32_t _p = (uint32_t)(parity); uint32_t _d; \
    asm volatile("{\n\t.reg .pred p;\n\t" \
        "mbarrier.try_wait.parity.acquire.cta.shared::cta.b64 p, [%1], %2;\n\t" \
        "selp.b32 %0, 1, 0, p;\n\t}" : "=r"(_d) : "r"(_m), "r"(_p) : "memory"); \
    if (!_d) { \
        asm volatile("{\n\t.reg .pred P1;\n\tWL_%=:\n\t" \
            "mbarrier.try_wait.parity.acquire.cta.shared::cta.b64 P1, [%0], %1, 0x989680;\n\t" \
            "@P1 bra.uni WD_%=;\n\tbra.uni WL_%=;\n\tWD_%=:\n\t}" \
            :: "r"(_m), "r"(_p) : "memory"); \
    } } while (0)

// ---------------- prep GEMM (gridDim.y = half): ----------------
// P[node][half*128 : half*128+128] = nf@W(half).T  (+ Pg[batch] if half==0)
__global__ __launch_bounds__(256, 1)
void prep_kernel(const float* __restrict__ nf, const int* __restrict__ batch, int Nn)
{
    extern __shared__ __align__(1024) char smem[];
    const uint32_t sbase = smem_u32(smem);
    const int tid  = threadIdx.x;
    const int wid  = tid >> 5;
    const int lane = tid & 31;
    const int blk  = blockIdx.x;
    const int half = blockIdx.y;
    const int c0      = half * 2;
    const int colbase = half * 128;
    const int addpg   = (half == 0);

    // copy W chunks c0, c0+1 (32KB) to smem[32768..65536)
    {
        const uint4* wsrc = (const uint4*)((const char*)g_Wimg + (size_t)c0 * SLAB);
        uint4* wdst = (uint4*)(smem + 32768);
        #pragma unroll
        for (int j = 0; j < 8; ++j)
            wdst[tid + j * 256] = wsrc[tid + j * 256];
    }
    // stage A: nf rows (2 slabs of 64 cols) fp32->fp16 swizzled
    {
        const int r = tid >> 1, q = tid & 1;
        int node = blk * TILE_E + r; if (node >= Nn) node = Nn - 1;
        const float* rp = nf + (size_t)node * DN;
        #pragma unroll
        for (int sl = 0; sl < 2; ++sl) {
            char* ab = smem + sl * SLAB;
            #pragma unroll
            for (int j = 0; j < 8; ++j) {
                const int col = q * 32 + j * 4;
                float4 v = *(const float4*)(rp + sl * 64 + col);
                __half2 a = __floats2half2_rn(v.x, v.y);
                __half2 b = __floats2half2_rn(v.z, v.w);
                uint2 pk; pk.x = *(uint32_t*)&a; pk.y = *(uint32_t*)&b;
                *(uint2*)(ab + SWZ128((uint32_t)(r * 128 + col * 2))) = pk;
            }
        }
    }
    __syncthreads();

    const int wm = wid & 3, wn = wid >> 2;
    float acc[2][8][4];
    #pragma unroll
    for (int mt = 0; mt < 2; ++mt)
        #pragma unroll
        for (int nt = 0; nt < 8; ++nt)
            #pragma unroll
            for (int z = 0; z < 4; ++z) acc[mt][nt][z] = 0.0f;

    #pragma unroll
    for (int sl = 0; sl < 2; ++sl) {
        const uint32_t Abase = sbase + sl * SLAB;
        const uint32_t Bbase = sbase + 32768 + sl * SLAB;
        #pragma unroll
        for (int ks = 0; ks < 4; ++ks) {
            uint32_t af[2][4], bf[4][4];
            {
                const int rofs = lane & 15;
                const int cofs = ks * 32 + ((lane >> 4) & 1) * 16;
                #pragma unroll
                for (int mt = 0; mt < 2; ++mt) {
                    const int row = wm * 32 + mt * 16 + rofs;
                    ldsm_x4(af[mt], Abase + SWZ128((uint32_t)(row * 128 + cofs)));
                }
            }
            {
                const int rofs = (lane & 7) + ((lane >> 4) & 1) * 8;
                const int cofs = ks * 32 + ((lane >> 3) & 1) * 16;
                #pragma unroll
                for (int nt = 0; nt < 4; ++nt) {
                    const int row = wn * 64 + nt * 16 + rofs;
                    ldsm_x4(bf[nt], Bbase + SWZ128((uint32_t)(row * 128 + cofs)));
                }
            }
            #pragma unroll
            for (int mt = 0; mt < 2; ++mt)
                #pragma unroll
                for (int nt = 0; nt < 4; ++nt) {
                    mma_f16(acc[mt][2 * nt + 0], af[mt], bf[nt][0], bf[nt][1]);
                    mma_f16(acc[mt][2 * nt + 1], af[mt], bf[nt][2], bf[nt][3]);
                }
        }
    }

    // epilogue: (+Pg[batch[n]]) -> fp16 store into g_P[n][colbase + col]
    #pragma unroll
    for (int mt = 0; mt < 2; ++mt) {
        const int n0 = blk * TILE_E + wm * 32 + mt * 16 + (lane >> 2);
        const int n1 = n0 + 8;
        #pragma unroll
        for (int nt = 0; nt < 8; ++nt) {
            const int col = wn * 64 + nt * 8 + (lane & 3) * 2;
            if (n0 < Nn) {
                float f0 = acc[mt][nt][0], f1 = acc[mt][nt][1];
                if (addpg) {
                    const float* pg = g_Pg + (size_t)batch[n0] * H + col;
                    f0 += pg[0]; f1 += pg[1];
                }
                __half2 hv = __floats2half2_rn(f0, f1);
                *(__half2*)(g_P + (size_t)n0 * 256 + colbase + col) = hv;
            }
            if (n1 < Nn) {
                float f0 = acc[mt][nt][2], f1 = acc[mt][nt][3];
                if (addpg) {
                    const float* pg = g_Pg + (size_t)batch[n1] * H + col;
                    f0 += pg[0]; f1 += pg[1];
                }
                __half2 hv = __floats2half2_rn(f0, f1);
                *(__half2*)(g_P + (size_t)n1 * 256 + colbase + col) = hv;
            }
        }
    }
}

// ---------------- main kernel ----------------
__global__ __launch_bounds__(THREADS, 1)
void edge_fact_kernel(const float* __restrict__ ef,
                      const int*   __restrict__ ei,
                      float*       __restrict__ out,
                      int E, int ntiles)
{
    extern __shared__ __align__(1024) char smem[];
    const uint32_t sbase = smem_u32(smem);
    const int tid  = threadIdx.x;
    const int wid  = tid >> 5;
    const int lane = tid & 31;

    // one-time: resident W3 (16KB = chunk 5) + mbarrier init
    {
        const uint4* wsrc = (const uint4*)((const char*)g_Wimg + 5 * SLAB);
        uint4* wdst = (uint4*)(smem + OFF_W3);
        #pragma unroll
        for (int j = 0; j < 3; ++j) {
            int i = tid + j * THREADS;
            if (i < 1024) wdst[i] = wsrc[i];
        }
    }
    if (tid == 0) {
        #pragma unroll
        for (int p = 0; p < 2; ++p) {
            MBAR_INIT(sbase + OFF_MBAR + p * 8, 128);        // full_ef[p]
            MBAR_INIT(sbase + OFF_MBAR + 16 + p * 8, 128);   // full_P[p]
            MBAR_INIT(sbase + OFF_MBAR + 32 + p * 8, NCONS); // empty[p]
        }
    }
    __syncthreads();

    if (wid >= 8) {
        // =================== PRODUCER (warps 8-11) ===================
        const int pw    = wid - 8;
        const int wrow0 = pw * 32;
        int* s_src = (int*)(smem + OFF_IDX);
        int* s_dst = s_src + TILE_E;
        const int l8 = lane & 7;
        const int r4 = lane >> 3;
        const int half = lane >> 4;        // 0: src-half, 1: dst-half
        const int li   = lane & 15;

        float4 ev[16];                     // ef prefetch: rows (g,r4), cols l8*4(+32)
        auto load_ef = [&](int tile) {
            #pragma unroll
            for (int g = 0; g < 8; ++g) {
                const int r = wrow0 + g * 4 + r4;
                int e = tile * TILE_E + r; if (e >= E) e = E - 1;
                const float* rp = ef + (size_t)e * DE;
                ev[2 * g]     = *(const float4*)(rp + l8 * 4);
                ev[2 * g + 1] = *(const float4*)(rp + 32 + l8 * 4);
            }
        };

        load_ef(blockIdx.x);               // prefetch tile 0

        int tcnt = 0;
        for (int tile = blockIdx.x; tile < ntiles; tile += gridDim.x, ++tcnt) {
            const int p = tcnt & 1;
            {
                int e = tile * TILE_E + wrow0 + lane; if (e >= E) e = E - 1;
                s_src[wrow0 + lane] = ei[e];
                s_dst[wrow0 + lane] = ei[E + e];
            }
            __syncwarp();

            if (tcnt >= 2) MBAR_WAIT(sbase + OFF_MBAR + 32 + p * 8, (((tcnt >> 1) & 1) ^ 1));

            // ---- P rows via cp.async: lanes 0-15 = P1'(src), 16-31 = P2(dst) ----
            {
                const uint32_t pb = sbase + OFF_P + p * PSTAGE;
                #pragma unroll
                for (int rp = 0; rp < 32; ++rp) {
                    const int r = wrow0 + rp;
                    const int idx = half ? s_dst[r] : s_src[r];
                    const char* src = (const char*)g_P + (size_t)idx * 512 + half * 256 + li * 16;
                    cp_async16(pb + r * PSTRIDE + lane * 16, src);
                }
                asm volatile("cp.async.commit_group;" ::: "memory");
            }

            // ---- ef slab: convert prefetched registers -> STS swizzled ----
            {
                char* dst = smem + OFF_EF + p * SLAB;
                #pragma unroll
                for (int g = 0; g < 8; ++g) {
                    const int r = wrow0 + g * 4 + r4;
                    float4 v0 = ev[2 * g], v1 = ev[2 * g + 1];
                    __half2 a0 = __floats2half2_rn(v0.x, v0.y);
                    __half2 b0 = __floats2half2_rn(v0.z, v0.w);
                    __half2 a1 = __floats2half2_rn(v1.x, v1.y);
                    __half2 b1 = __floats2half2_rn(v1.z, v1.w);
                    uint2 p0; p0.x = *(uint32_t*)&a0; p0.y = *(uint32_t*)&b0;
                    uint2 p1; p1.x = *(uint32_t*)&a1; p1.y = *(uint32_t*)&b1;
                    *(uint2*)(dst + SWZ128((uint32_t)(r * 128 + l8 * 8)))      = p0;
                    *(uint2*)(dst + SWZ128((uint32_t)(r * 128 + 64 + l8 * 8))) = p1;
                }
            }
            MBAR_ARRIVE(sbase + OFF_MBAR + p * 8);          // full_ef

            // prefetch ef for next tile (latency hidden under consumer compute)
            if (tile + gridDim.x < ntiles) load_ef(tile + gridDim.x);

            asm volatile("cp.async.wait_group 0;" ::: "memory");
            MBAR_ARRIVE(sbase + OFF_MBAR + 16 + p * 8);     // full_P
        }
    } else {
        // =================== CONSUMER (warps 0-7) ===================
        const int wm = wid & 3;
        const int wn = wid >> 2;
        int tcnt = 0;
        for (int tile = blockIdx.x; tile < ntiles; tile += gridDim.x, ++tcnt) {
            const int p  = tcnt & 1;
            const uint32_t fw = (tcnt >> 1) & 1;
            const int e0 = tile * TILE_E;

            float acc[2][8][4];
            #pragma unroll
            for (int mt = 0; mt < 2; ++mt)
                #pragma unroll
                for (int nt = 0; nt < 8; ++nt)
                    #pragma unroll
                    for (int z = 0; z < 4; ++z) acc[mt][nt][z] = 0.0f;

            MBAR_WAIT(sbase + OFF_MBAR + p * 8, fw);        // full_ef

            // ---- single K=64 slab: A=ef, B=W3 resident ----
            {
                const uint32_t Abase = sbase + OFF_EF + p * SLAB;
                const uint32_t Bbase = sbase + OFF_W3;
                #pragma unroll
                for (int ks = 0; ks < 4; ++ks) {
                    uint32_t af[2][4], bf[4][4];
                    {
                        const int rofs = lane & 15;
                        const int cofs = ks * 32 + ((lane >> 4) & 1) * 16;
                        #pragma unroll
                        for (int mt = 0; mt < 2; ++mt) {
                            const int row = wm * 32 + mt * 16 + rofs;
                            ldsm_x4(af[mt], Abase + SWZ128((uint32_t)(row * 128 + cofs)));
                        }
                    }
                    {
                        const int rofs = (lane & 7) + ((lane >> 4) & 1) * 8;
                        const int cofs = ks * 32 + ((lane >> 3) & 1) * 16;
                        #pragma unroll
                        for (int nt = 0; nt < 4; ++nt) {
                            const int row = wn * 64 + nt * 16 + rofs;
                            ldsm_x4(bf[nt], Bbase + SWZ128((uint32_t)(row * 128 + cofs)));
                        }
                    }
                    #pragma unroll
                    for (int mt = 0; mt < 2; ++mt)
                        #pragma unroll
                        for (int nt = 0; nt < 4; ++nt) {
                            mma_f16(acc[mt][2 * nt + 0], af[mt], bf[nt][0], bf[nt][1]);
                            mma_f16(acc[mt][2 * nt + 1], af[mt], bf[nt][2], bf[nt][3]);
                        }
                }
            }

            MBAR_WAIT(sbase + OFF_MBAR + 16 + p * 8, fw);   // full_P

            // ---- epilogue: + P1'[src] + P2[dst], softplus, store ----
            const char* pb = smem + OFF_P + p * PSTAGE;
            #pragma unroll
            for (int mt = 0; mt < 2; ++mt) {
                const int lr0 = wm * 32 + mt * 16 + (lane >> 2);
                const int lr1 = lr0 + 8;
                const int r0 = e0 + lr0, r1 = e0 + lr1;
                #pragma unroll
                for (int nt = 0; nt < 8; ++nt) {
                    const int col  = wn * 64 + nt * 8 + (lane & 3) * 2;
                    const int colb = col * 2;
                    if (r0 < E) {
                        uint32_t u1 = *(const uint32_t*)(pb + lr0 * PSTRIDE + colb);
                        uint32_t u2 = *(const uint32_t*)(pb + lr0 * PSTRIDE + 256 + colb);
                        float2 f1 = __half22float2(*(__half2*)&u1);
                        float2 f2 = __half22float2(*(__half2*)&u2);
                        float2 o;
                        o.x = softplus_shift(acc[mt][nt][0] + f1.x + f2.x);
                        o.y = softplus_shift(acc[mt][nt][1] + f1.y + f2.y);
                        *(float2*)(out + (size_t)r0 * H + col) = o;
                    }
                    if (r1 < E) {
                        uint32_t u1 = *(const uint32_t*)(pb + lr1 * PSTRIDE + colb);
                        uint32_t u2 = *(const uint32_t*)(pb + lr1 * PSTRIDE + 256 + colb);
                        float2 f1 = __half22float2(*(__half2*)&u1);
                        float2 f2 = __half22float2(*(__half2*)&u2);
                        float2 o;
                        o.x = softplus_shift(acc[mt][nt][2] + f1.x + f2.x);
                        o.y = softplus_shift(acc[mt][nt][3] + f1.y + f2.y);
                        *(float2*)(out + (size_t)r1 * H + col) = o;
                    }
                }
            }
            MBAR_ARRIVE(sbase + OFF_MBAR + 32 + p * 8);     // empty
        }
    }
}

extern "C" void kernel_launch(void* const* d_in, const int* in_sizes, int n_in,
                              void* d_out, int out_size)
{
    const float* nf    = (const float*)d_in[0];
    const float* ef    = (const float*)d_in[1];
    const float* gf    = (const float*)d_in[2];
    const int*   ei    = (const int*)d_in[3];
    const int*   batch = (const int*)d_in[4];
    const float* W     = (const float*)d_in[5];
    float*       out   = (float*)d_out;

    const int E  = in_sizes[1] / DE;             // edge_feats is [E, 64]
    const int Nn = in_sizes[0] / DN;
    const int G  = in_sizes[2] / DG;
    const int ntiles = (E + TILE_E - 1) / TILE_E;

    static int sms = 0;
    if (sms == 0) {
        cudaDeviceGetAttribute(&sms, cudaDevAttrMultiProcessorCount, 0);
        if (sms <= 0) sms = 148;
        cudaFuncSetAttribute(edge_fact_kernel,
                             cudaFuncAttributeMaxDynamicSharedMemorySize, SMEM_TOTAL);
        cudaFuncSetAttribute(prep_kernel,
                             cudaFuncAttributeMaxDynamicSharedMemorySize, 65536);
    }

    w_convert_kernel<<<(H * 384 + 255) / 256, 256>>>(W);
    pg_kernel<<<(G * H + 255) / 256, 256>>>(gf, W, G);
    const int nblk = (Nn + TILE_E - 1) / TILE_E;
    prep_kernel<<<dim3(nblk, 2), 256, 65536>>>(nf, batch, Nn);   // both halves concurrent

    const int grid = (sms < ntiles) ? sms : ntiles;
    edge_fact_kernel<<<grid, THREADS, SMEM_TOTAL>>>(ef, ei, out, E, ntiles);
}